// round 1
// baseline (speedup 1.0000x reference)
#include <cuda_runtime.h>

// VolumeRenderer: NeRF-style compositing.
//   deltas = diff(depth) with 1e10 sentinel at the end
//   att    = exp(-density * deltas)
//   T      = inclusive cumprod(att)
//   w      = T * (1 - att)
//   feat_out[n,c]  = sum_s w[n,s] * feature[n,s,c]
//   depth_out[n]   = sum_s w[n,s] * depth[n,s]
//
// Layout: one warp per ray. Lane l owns samples [4l, 4l+3] (blocked), so
// density/depth are one float4 per lane (512 B contiguous per warp) and
// feature is three float4 per lane (1536 B contiguous per warp).
// Output buffer: feat_out flattened (N_RAYS*3 floats) followed by depth_out
// (N_RAYS floats).

#define N_RAYS    131072
#define N_SAMPLES 128
#define FAR_DELTA 1e10f

__global__ __launch_bounds__(256, 8)
void volrend_kernel(const float* __restrict__ density,
                    const float* __restrict__ feature,
                    const float* __restrict__ depth,
                    float* __restrict__ out)
{
    const unsigned FULL = 0xffffffffu;
    int gwarp = (blockIdx.x * blockDim.x + threadIdx.x) >> 5;
    int lane  = threadIdx.x & 31;
    if (gwarp >= N_RAYS) return;
    long r = gwarp;

    // ---- coalesced float4 loads ----
    const float4* d4p = reinterpret_cast<const float4*>(density + r * N_SAMPLES);
    const float4* z4p = reinterpret_cast<const float4*>(depth   + r * N_SAMPLES);
    const float4* f4p = reinterpret_cast<const float4*>(feature + r * (N_SAMPLES * 3));

    float4 dn = d4p[lane];
    float4 z  = z4p[lane];
    float4 f0 = f4p[lane * 3 + 0];
    float4 f1 = f4p[lane * 3 + 1];
    float4 f2 = f4p[lane * 3 + 2];

    // depth of first sample in the NEXT lane (needed for this lane's 4th delta)
    float z_next = __shfl_down_sync(FULL, z.x, 1);

    float del0 = z.y - z.x;
    float del1 = z.z - z.y;
    float del2 = z.w - z.z;
    float del3 = (lane == 31) ? FAR_DELTA : (z_next - z.w);

    float a0 = __expf(-dn.x * del0);
    float a1 = __expf(-dn.y * del1);
    float a2 = __expf(-dn.z * del2);
    float a3 = __expf(-dn.w * del3);

    // local inclusive products within the lane's 4 samples
    float p0 = a0;
    float p1 = p0 * a1;
    float p2 = p1 * a2;
    float p3 = p2 * a3;

    // warp-inclusive scan (product) of per-lane totals, then shift to exclusive
    float s = p3;
    #pragma unroll
    for (int off = 1; off < 32; off <<= 1) {
        float v = __shfl_up_sync(FULL, s, off);
        if (lane >= off) s *= v;
    }
    float excl = __shfl_up_sync(FULL, s, 1);
    if (lane == 0) excl = 1.0f;

    // inclusive transmittance per sample, then weights
    float w0 = (excl * p0) * (1.0f - a0);
    float w1 = (excl * p1) * (1.0f - a1);
    float w2 = (excl * p2) * (1.0f - a2);
    float w3 = (excl * p3) * (1.0f - a3);

    // feature accumulation: sample 4l+k channels unpacked from the 3 float4s
    //   s0 = (f0.x f0.y f0.z)  s1 = (f0.w f1.x f1.y)
    //   s2 = (f1.z f1.w f2.x)  s3 = (f2.y f2.z f2.w)
    float fx = w0 * f0.x + w1 * f0.w + w2 * f1.z + w3 * f2.y;
    float fy = w0 * f0.y + w1 * f1.x + w2 * f1.w + w3 * f2.z;
    float fz = w0 * f0.z + w1 * f1.y + w2 * f2.x + w3 * f2.w;
    float ds = w0 * z.x  + w1 * z.y  + w2 * z.z  + w3 * z.w;

    // warp reduction of the 4 accumulators
    #pragma unroll
    for (int off = 16; off > 0; off >>= 1) {
        fx += __shfl_xor_sync(FULL, fx, off);
        fy += __shfl_xor_sync(FULL, fy, off);
        fz += __shfl_xor_sync(FULL, fz, off);
        ds += __shfl_xor_sync(FULL, ds, off);
    }

    if (lane == 0) {
        out[r * 3 + 0] = fx;
        out[r * 3 + 1] = fy;
        out[r * 3 + 2] = fz;
        out[(long)N_RAYS * 3 + r] = ds;
    }
}

extern "C" void kernel_launch(void* const* d_in, const int* in_sizes, int n_in,
                              void* d_out, int out_size)
{
    const float* density = (const float*)d_in[0];
    const float* feature = (const float*)d_in[1];
    const float* depth   = (const float*)d_in[2];
    float* out = (float*)d_out;

    // one warp per ray, 256 threads = 8 warps per block
    int blocks = N_RAYS / 8;
    volrend_kernel<<<blocks, 256>>>(density, feature, depth, out);
}

// round 2
// speedup vs baseline: 1.0210x; 1.0210x over previous
#include <cuda_runtime.h>

// VolumeRenderer: NeRF-style compositing. One warp per ray; lane l owns
// samples [4l, 4l+3]. All inputs streamed once via __ldcs (evict-first).
//
//   deltas = diff(depth) with 1e10 sentinel
//   att    = exp(-density * deltas)
//   T      = inclusive cumprod(att)   (lane-local products + warp shfl scan)
//   w      = T * (1 - att)
//   feat_out[n,c] = sum_s w*feature ; depth_out[n] = sum_s w*depth
//
// Output: feat_out (N_RAYS*3 floats) then depth_out (N_RAYS floats).

#define N_RAYS    131072
#define N_SAMPLES 128
#define FAR_DELTA 1e10f

__global__ __launch_bounds__(256, 8)
void volrend_kernel(const float* __restrict__ density,
                    const float* __restrict__ feature,
                    const float* __restrict__ depth,
                    float* __restrict__ out)
{
    const unsigned FULL = 0xffffffffu;
    int gwarp = (blockIdx.x * blockDim.x + threadIdx.x) >> 5;
    int lane  = threadIdx.x & 31;
    if (gwarp >= N_RAYS) return;
    long r = gwarp;

    // ---- coalesced float4 streaming loads (evict-first: single-touch data) ----
    const float4* d4p = reinterpret_cast<const float4*>(density + r * N_SAMPLES);
    const float4* z4p = reinterpret_cast<const float4*>(depth   + r * N_SAMPLES);
    const float4* f4p = reinterpret_cast<const float4*>(feature + r * (N_SAMPLES * 3));

    float4 dn = __ldcs(d4p + lane);
    float4 z  = __ldcs(z4p + lane);
    float4 f0 = __ldcs(f4p + lane * 3 + 0);
    float4 f1 = __ldcs(f4p + lane * 3 + 1);
    float4 f2 = __ldcs(f4p + lane * 3 + 2);

    // depth of first sample in the NEXT lane (this lane's 4th delta)
    float z_next = __shfl_down_sync(FULL, z.x, 1);

    float del0 = z.y - z.x;
    float del1 = z.z - z.y;
    float del2 = z.w - z.z;
    float del3 = (lane == 31) ? FAR_DELTA : (z_next - z.w);

    float a0 = __expf(-dn.x * del0);
    float a1 = __expf(-dn.y * del1);
    float a2 = __expf(-dn.z * del2);
    float a3 = __expf(-dn.w * del3);

    // lane-local inclusive products
    float p0 = a0;
    float p1 = p0 * a1;
    float p2 = p1 * a2;
    float p3 = p2 * a3;

    // warp-inclusive product scan of lane totals -> exclusive prefix
    float s = p3;
    #pragma unroll
    for (int off = 1; off < 32; off <<= 1) {
        float v = __shfl_up_sync(FULL, s, off);
        if (lane >= off) s *= v;
    }
    float excl = __shfl_up_sync(FULL, s, 1);
    if (lane == 0) excl = 1.0f;

    // weights
    float w0 = (excl * p0) * (1.0f - a0);
    float w1 = (excl * p1) * (1.0f - a1);
    float w2 = (excl * p2) * (1.0f - a2);
    float w3 = (excl * p3) * (1.0f - a3);

    // feature dot products; sample k channels unpacked from the 3 float4s:
    //   s0 = (f0.x f0.y f0.z)  s1 = (f0.w f1.x f1.y)
    //   s2 = (f1.z f1.w f2.x)  s3 = (f2.y f2.z f2.w)
    float fx = w0 * f0.x + w1 * f0.w + w2 * f1.z + w3 * f2.y;
    float fy = w0 * f0.y + w1 * f1.x + w2 * f1.w + w3 * f2.z;
    float fz = w0 * f0.z + w1 * f1.y + w2 * f2.x + w3 * f2.w;
    float ds = w0 * z.x  + w1 * z.y  + w2 * z.z  + w3 * z.w;

    // warp reduction of the 4 accumulators
    #pragma unroll
    for (int off = 16; off > 0; off >>= 1) {
        fx += __shfl_xor_sync(FULL, fx, off);
        fy += __shfl_xor_sync(FULL, fy, off);
        fz += __shfl_xor_sync(FULL, fz, off);
        ds += __shfl_xor_sync(FULL, ds, off);
    }

    // after the xor-butterfly every lane holds the sums; spread the 4 stores
    if (lane == 0)      out[r * 3 + 0] = fx;
    else if (lane == 1) out[r * 3 + 1] = fy;
    else if (lane == 2) out[r * 3 + 2] = fz;
    else if (lane == 3) out[(long)N_RAYS * 3 + r] = ds;
}

extern "C" void kernel_launch(void* const* d_in, const int* in_sizes, int n_in,
                              void* d_out, int out_size)
{
    const float* density = (const float*)d_in[0];
    const float* feature = (const float*)d_in[1];
    const float* depth   = (const float*)d_in[2];
    float* out = (float*)d_out;

    int blocks = N_RAYS / 8;   // one warp per ray, 8 warps (256 threads) per block
    volrend_kernel<<<blocks, 256>>>(density, feature, depth, out);
}